// round 12
// baseline (speedup 1.0000x reference)
#include <cuda_runtime.h>
#include <cuda_fp16.h>
#include <math.h>
#include <stdint.h>

// Problem constants
#define Bb   2
#define Ls   2048
#define Dd   1024
#define Hh   16
#define DHd  64
#define FFd  4096
#define Mrows (Bb*Ls)      // 4096
#define LD    (Ls*Dd)      // 2097152
#define NPART 64
#define QKVD (3*Dd)        // 3072

// ---------------- scratch (static device globals; no allocation) -------------
__device__ float g_r1[Mrows*Dd];
__device__ float g_part[Bb*NPART*2];
__device__ float g_stats[Bb*2];
__device__ float g_bqkv[QKVD];

// fp16 buffers
__device__ __align__(256) __half g_wqkv[QKVD*Dd];     // wq|wk|wv rows
__device__ __align__(256) __half g_wo[Dd*Dd];
__device__ __align__(256) __half g_w1[FFd*Dd];
__device__ __align__(256) __half g_w2[Dd*FFd];
__device__ __align__(256) __half g_h[Mrows*Dd];
__device__ __align__(256) __half g_y[Mrows*Dd];
__device__ __align__(256) __half g_f[Mrows*FFd];
__device__ __align__(256) __half g_oH[Mrows*Dd];
__device__ __align__(256) __half g_qkv[Mrows*QKVD];   // [tok, 3072]

// ---------------- PTX helpers (all legal on plain sm_103) ---------------------
__device__ __forceinline__ uint32_t smem_u32(const void* p) {
    uint32_t a;
    asm("{ .reg .u64 t; cvta.to.shared.u64 t, %1; cvt.u32.u64 %0, t; }" : "=r"(a) : "l"(p));
    return a;
}
__device__ __forceinline__ void cp16(uint32_t dst, const void* src) {
    asm volatile("cp.async.cg.shared.global [%0], [%1], 16;" :: "r"(dst), "l"(src) : "memory");
}
__device__ __forceinline__ void ldsm4(uint32_t* r, uint32_t addr) {
    asm volatile("ldmatrix.sync.aligned.m8n8.x4.shared.b16 {%0,%1,%2,%3}, [%4];"
                 : "=r"(r[0]), "=r"(r[1]), "=r"(r[2]), "=r"(r[3]) : "r"(addr));
}
__device__ __forceinline__ void ldsm4t(uint32_t* r, uint32_t addr) {
    asm volatile("ldmatrix.sync.aligned.m8n8.x4.trans.shared.b16 {%0,%1,%2,%3}, [%4];"
                 : "=r"(r[0]), "=r"(r[1]), "=r"(r[2]), "=r"(r[3]) : "r"(addr));
}
__device__ __forceinline__ void mma_f16(float* c, const uint32_t* a, uint32_t b0, uint32_t b1) {
    asm volatile(
        "mma.sync.aligned.m16n8k16.row.col.f32.f16.f16.f32 "
        "{%0,%1,%2,%3}, {%4,%5,%6,%7}, {%8,%9}, {%0,%1,%2,%3};"
        : "+f"(c[0]), "+f"(c[1]), "+f"(c[2]), "+f"(c[3])
        : "r"(a[0]), "r"(a[1]), "r"(a[2]), "r"(a[3]), "r"(b0), "r"(b1));
}
__device__ __forceinline__ uint32_t f2h2(float lo, float hi) {
    __half2 t = __floats2half2_rn(lo, hi);
    return *reinterpret_cast<uint32_t*>(&t);
}
__device__ __forceinline__ float ex2(float x) {
    float r;
    asm("ex2.approx.f32 %0, %1;" : "=f"(r) : "f"(x));
    return r;
}
#define SCL_LOG2 0.36067376022224085f   // 0.25 * log2(e)

// ---------------- fp32 -> fp16 convert (weights), 4x float4 per thread --------
__global__ void conv_kernel(const float* __restrict__ in, __half* __restrict__ outp) {
    const int base = (blockIdx.x * 256 + threadIdx.x) * 4;   // float4 index
    #pragma unroll
    for (int i = 0; i < 4; i++) {
        float4 v = ((const float4*)in)[base + i];
        ((uint32_t*)outp)[2*(base+i)]   = f2h2(v.x, v.y);
        ((uint32_t*)outp)[2*(base+i)+1] = f2h2(v.z, v.w);
    }
}

// concat biases bq|bk|bv -> g_bqkv
__global__ void bias_concat(const float* __restrict__ bq, const float* __restrict__ bk,
                            const float* __restrict__ bv) {
    const int i = blockIdx.x * 256 + threadIdx.x;   // 0..3071
    const float v = (i < Dd) ? bq[i] : (i < 2*Dd) ? bk[i - Dd] : bv[i - 2*Dd];
    g_bqkv[i] = v;
}

// ---------------- LayerNorm over (L,D) jointly per batch ---------------------
__global__ void ln_partial(const float* __restrict__ x) {
    const int b = blockIdx.y;
    const int tid = threadIdx.x;
    const int chunk4 = (LD / NPART) / 4;
    const float4* xp = (const float4*)(x + (size_t)b * LD) + (size_t)blockIdx.x * chunk4;
    float s = 0.f, s2 = 0.f;
    for (int i = tid; i < chunk4; i += 256) {
        float4 v = xp[i];
        s  += v.x + v.y + v.z + v.w;
        s2 += v.x*v.x + v.y*v.y + v.z*v.z + v.w*v.w;
    }
    __shared__ float sh[2][256];
    sh[0][tid] = s; sh[1][tid] = s2;
    __syncthreads();
    for (int st = 128; st > 0; st >>= 1) {
        if (tid < st) { sh[0][tid] += sh[0][tid+st]; sh[1][tid] += sh[1][tid+st]; }
        __syncthreads();
    }
    if (tid == 0) {
        g_part[(b*NPART + blockIdx.x)*2 + 0] = sh[0][0];
        g_part[(b*NPART + blockIdx.x)*2 + 1] = sh[1][0];
    }
}

__global__ void ln_final() {
    const int b = blockIdx.x, t = threadIdx.x;   // 32 threads
    float s  = g_part[(b*NPART + t)*2 + 0] + g_part[(b*NPART + t + 32)*2 + 0];
    float s2 = g_part[(b*NPART + t)*2 + 1] + g_part[(b*NPART + t + 32)*2 + 1];
    for (int o = 16; o; o >>= 1) {
        s  += __shfl_xor_sync(0xffffffffu, s,  o);
        s2 += __shfl_xor_sync(0xffffffffu, s2, o);
    }
    if (t == 0) {
        float mu  = s / (float)LD;
        float var = s2 / (float)LD - mu*mu;
        g_stats[b*2 + 0] = mu;
        g_stats[b*2 + 1] = rsqrtf(var + 1e-5f);
    }
}

// normalize, emit single fp16; 4x float4 per thread
__global__ void ln_apply_h(const float* __restrict__ in, __half* __restrict__ outp) {
    const int base = (blockIdx.x * 256 + threadIdx.x) * 4;   // float4 index
    const int b = base / (LD/4);
    const float mu = g_stats[b*2 + 0], rs = g_stats[b*2 + 1];
    #pragma unroll
    for (int i = 0; i < 4; i++) {
        float4 v = ((const float4*)in)[base + i];
        ((uint32_t*)outp)[2*(base+i)]   = f2h2((v.x - mu)*rs, (v.y - mu)*rs);
        ((uint32_t*)outp)[2*(base+i)+1] = f2h2((v.z - mu)*rs, (v.w - mu)*rs);
    }
}

// ---------------- mma.sync fp16 GEMM ------------------------------------------
// C[M,N] = A[M,K] @ W[N,K]^T, fp32 accum, 128x128 tile, BK=32, 3-stage cp.async.
#define TILE_B   10240              // 128 * 80
#define STAGE_B  (2*TILE_B)         // 20480
#define GEMM_SMEM (3*STAGE_B)       // 61440

// OUT: 0 = fp32 C, 1 = fp16 Ch
template<bool RELU, bool RESID, int OUT>
__global__ __launch_bounds__(256)
void gemm_mma(const __half* __restrict__ A, const __half* __restrict__ W,
              const float* __restrict__ bias, const float* __restrict__ R,
              float* __restrict__ C, __half* __restrict__ Ch,
              int Ndim, int Kdim)
{
    extern __shared__ char smem[];
    const uint32_t sb = smem_u32(smem);
    const int tid  = threadIdx.x;
    const int wid  = tid >> 5, lane = tid & 31;
    const int wm   = wid & 3;
    const int wn   = wid >> 2;
    const int bm   = blockIdx.y * 128, bn = blockIdx.x * 128;

    float acc[2][8][4];
    #pragma unroll
    for (int i = 0; i < 2; i++)
        #pragma unroll
        for (int j = 0; j < 8; j++)
            #pragma unroll
            for (int t = 0; t < 4; t++) acc[i][j][t] = 0.f;

    const int r0c = tid >> 2, c0c = tid & 3;
    const int r1c = (tid + 256) >> 2, c1c = tid & 3;

    auto load_stage = [&](int s, int k0) {
        const uint32_t st = sb + s * STAGE_B;
        cp16(st + 0*TILE_B + r0c*80 + c0c*16, A + (size_t)(bm + r0c)*Kdim + k0 + c0c*8);
        cp16(st + 0*TILE_B + r1c*80 + c1c*16, A + (size_t)(bm + r1c)*Kdim + k0 + c1c*8);
        cp16(st + 1*TILE_B + r0c*80 + c0c*16, W + (size_t)(bn + r0c)*Kdim + k0 + c0c*8);
        cp16(st + 1*TILE_B + r1c*80 + c1c*16, W + (size_t)(bn + r1c)*Kdim + k0 + c1c*8);
        asm volatile("cp.async.commit_group;" ::: "memory");
    };

    const int nk = Kdim >> 5;
    load_stage(0, 0);
    load_stage(1, 32);

    for (int kt = 0; kt < nk; kt++) {
        if (kt + 1 < nk) { asm volatile("cp.async.wait_group 1;" ::: "memory"); }
        else             { asm volatile("cp.async.wait_group 0;" ::: "memory"); }
        __syncthreads();
        if (kt + 2 < nk) load_stage((kt + 2) % 3, (kt + 2) << 5);

        const uint32_t st = sb + (kt % 3) * STAGE_B;
        #pragma unroll
        for (int ks = 0; ks < 2; ks++) {
            const uint32_t koff = ks*32 + ((lane >> 4) & 1)*16;
            uint32_t a[2][4];
            #pragma unroll
            for (int mt = 0; mt < 2; mt++)
                ldsm4(a[mt], st + (wm*32 + mt*16 + (lane & 15))*80 + koff);
            #pragma unroll
            for (int g = 0; g < 4; g++) {
                const uint32_t rb = st + TILE_B + (wn*64 + g*16 + (lane & 15))*80 + koff;
                uint32_t wv[4];
                ldsm4(wv, rb);
                #pragma unroll
                for (int mt = 0; mt < 2; mt++) {
                    mma_f16(acc[mt][2*g],   a[mt], wv[0], wv[2]);
                    mma_f16(acc[mt][2*g+1], a[mt], wv[1], wv[3]);
                }
            }
        }
    }

    // ---- epilogue ----
    #pragma unroll
    for (int mt = 0; mt < 2; mt++) {
        const int row0 = bm + wm*32 + mt*16 + (lane >> 2);
        #pragma unroll
        for (int nt = 0; nt < 8; nt++) {
            const int cc = bn + wn*64 + nt*8 + (lane & 3)*2;
            const float b0 = bias[cc], b1 = bias[cc+1];
            float v00 = acc[mt][nt][0] + b0, v01 = acc[mt][nt][1] + b1;
            float v10 = acc[mt][nt][2] + b0, v11 = acc[mt][nt][3] + b1;
            if (RESID) {
                v00 += R[(size_t)row0*Ndim + cc];     v01 += R[(size_t)row0*Ndim + cc + 1];
                v10 += R[(size_t)(row0+8)*Ndim + cc]; v11 += R[(size_t)(row0+8)*Ndim + cc + 1];
            }
            if (RELU) {
                v00 = fmaxf(v00, 0.f); v01 = fmaxf(v01, 0.f);
                v10 = fmaxf(v10, 0.f); v11 = fmaxf(v11, 0.f);
            }
            if (OUT == 0) {
                *(float2*)(C + (size_t)row0*Ndim + cc)     = {v00, v01};
                *(float2*)(C + (size_t)(row0+8)*Ndim + cc) = {v10, v11};
            } else {
                *(uint32_t*)(Ch + (size_t)row0*Ndim + cc)     = f2h2(v00, v01);
                *(uint32_t*)(Ch + (size_t)(row0+8)*Ndim + cc) = f2h2(v10, v11);
            }
        }
    }
}

// ---------------- MMA flash attention (single-term fp16) ----------------------
// Per CTA: one (b, h), 128 q rows. 8 warps x 16 q rows.
// Q/K/V read from fused qkv[tok, 3072]; KV streamed in 64-key chunks, 3-stage.
#define AST 144
#define ATT_Q  0
#define ATT_S0 (128*AST)             // 18432
#define ATT_STAGE (2*64*AST)         // 18432 (K tile + V tile)
#define ATT_Vo (64*AST)
#define ATT_SMEM (ATT_S0 + 3*ATT_STAGE)   // 73728

__global__ __launch_bounds__(256)
void attn_mma(const __half* __restrict__ qkv_g, __half* __restrict__ o_g)
{
    extern __shared__ char smem[];
    const uint32_t sb = smem_u32(smem);
    const int tid = threadIdx.x, w = tid >> 5, lane = tid & 31;
    const int b = blockIdx.z, h = blockIdx.y, q0 = blockIdx.x * 128;
    const size_t tokbase = (size_t)(b*Ls + q0);
    const int coff = h * DHd;
    const __half* q_g = qkv_g + coff;
    const __half* k_g = qkv_g + Dd   + coff;
    const __half* v_g = qkv_g + 2*Dd + coff;

    // load Q tile, 128 rows x 128B
    #pragma unroll
    for (int it = 0; it < 4; it++) {
        const int unit = tid + it*256;
        const int r = unit >> 3, c = unit & 7;
        cp16(sb + ATT_Q + r*AST + c*16, q_g + (tokbase + r)*QKVD + c*8);
    }
    asm volatile("cp.async.commit_group;" ::: "memory");

    auto load_kv = [&](int s, int t0) {
        const uint32_t st = sb + ATT_S0 + s*ATT_STAGE;
        const size_t kb = (size_t)(b*Ls + t0);
        #pragma unroll
        for (int it = 0; it < 2; it++) {
            const int unit = tid + it*256;
            const int r = unit >> 3, c = unit & 7;
            cp16(st + r*AST + c*16,          k_g + (kb + r)*QKVD + c*8);
            cp16(st + ATT_Vo + r*AST + c*16, v_g + (kb + r)*QKVD + c*8);
        }
        asm volatile("cp.async.commit_group;" ::: "memory");
    };

    load_kv(0, 0);
    load_kv(1, 64);
    asm volatile("cp.async.wait_group 1;" ::: "memory");   // Q + kv0 ready
    __syncthreads();

    // Q fragments in registers (A operand, m16 rows = w*16)
    uint32_t qf[4][4];
    #pragma unroll
    for (int kc = 0; kc < 4; kc++)
        ldsm4(qf[kc], sb + ATT_Q + (w*16 + (lane & 15))*AST + kc*32 + ((lane >> 4) & 1)*16);

    float oacc[8][4];
    #pragma unroll
    for (int g = 0; g < 8; g++)
        #pragma unroll
        for (int i = 0; i < 4; i++) oacc[g][i] = 0.f;
    float m0 = -1e30f, m1 = -1e30f, l0 = 0.f, l1 = 0.f;

    const int nt = Ls/64;
    for (int t = 0; t < nt; t++) {
        if (t > 0) {
            if (t + 1 < nt) { asm volatile("cp.async.wait_group 1;" ::: "memory"); }
            else            { asm volatile("cp.async.wait_group 0;" ::: "memory"); }
            __syncthreads();
        }
        if (t + 2 < nt) load_kv((t + 2) % 3, (t + 2) * 64);
        const uint32_t st = sb + ATT_S0 + (t % 3)*ATT_STAGE;

        // ---- S = Q @ K^T ----
        float sc[8][4];
        #pragma unroll
        for (int g = 0; g < 8; g++)
            #pragma unroll
            for (int i = 0; i < 4; i++) sc[g][i] = 0.f;
        #pragma unroll
        for (int ng = 0; ng < 4; ng++) {
            #pragma unroll
            for (int kc = 0; kc < 4; kc++) {
                uint32_t bh[4];
                ldsm4(bh, st + (ng*16 + (lane & 15))*AST + kc*32 + ((lane >> 4) & 1)*16);
                mma_f16(sc[2*ng],   qf[kc], bh[0], bh[2]);
                mma_f16(sc[2*ng+1], qf[kc], bh[1], bh[3]);
            }
        }

        // ---- online softmax in log2 domain (scale folded: 0.25*log2e) ----
        float rm0 = -1e30f, rm1 = -1e30f;
        #pragma unroll
        for (int g = 0; g < 8; g++) {
            sc[g][0] *= SCL_LOG2; sc[g][1] *= SCL_LOG2;
            sc[g][2] *= SCL_LOG2; sc[g][3] *= SCL_LOG2;
            rm0 = fmaxf(rm0, fmaxf(sc[g][0], sc[g][1]));
            rm1 = fmaxf(rm1, fmaxf(sc[g][2], sc[g][3]));
        }
        rm0 = fmaxf(rm0, __shfl_xor_sync(0xffffffffu, rm0, 1));
        rm0 = fmaxf(rm0, __shfl_xor_sync(0xffffffffu, rm0, 2));
        rm1 = fmaxf(rm1, __shfl_xor_sync(0xffffffffu, rm1, 1));
        rm1 = fmaxf(rm1, __shfl_xor_sync(0xffffffffu, rm1, 2));
        const float nm0 = fmaxf(m0, rm0), nm1 = fmaxf(m1, rm1);
        const float c0 = ex2(m0 - nm0), c1 = ex2(m1 - nm1);
        m0 = nm0; m1 = nm1;

        float ls0 = 0.f, ls1 = 0.f;
        uint32_t pf[4][4];
        #pragma unroll
        for (int g = 0; g < 8; g++) {
            const float p0 = ex2(sc[g][0] - m0);
            const float p1 = ex2(sc[g][1] - m0);
            const float p2 = ex2(sc[g][2] - m1);
            const float p3 = ex2(sc[g][3] - m1);
            ls0 += p0 + p1; ls1 += p2 + p3;
            const uint32_t hp01 = f2h2(p0, p1), hp23 = f2h2(p2, p3);
            const int kc = g >> 1;
            if ((g & 1) == 0) { pf[kc][0] = hp01; pf[kc][1] = hp23; }
            else              { pf[kc][2] = hp01; pf[kc][3] = hp23; }
            oacc[g][0] *= c0; oacc[g][1] *= c0; oacc[g][2] *= c1; oacc[g][3] *= c1;
        }
        ls0 += __shfl_xor_sync(0xffffffffu, ls0, 1);
        ls0 += __shfl_xor_sync(0xffffffffu, ls0, 2);
        ls1 += __shfl_xor_sync(0xffffffffu, ls1, 1);
        ls1 += __shfl_xor_sync(0xffffffffu, ls1, 2);
        l0 = l0*c0 + ls0; l1 = l1*c1 + ls1;

        // ---- O += P @ V, V^T via ldmatrix.trans ----
        #pragma unroll
        for (int ng = 0; ng < 4; ng++) {
            #pragma unroll
            for (int kc = 0; kc < 4; kc++) {
                uint32_t vv[4];
                ldsm4t(vv, st + ATT_Vo + (kc*16 + (lane & 15))*AST + ng*32 + ((lane >> 4) & 1)*16);
                mma_f16(oacc[2*ng],   pf[kc], vv[0], vv[1]);
                mma_f16(oacc[2*ng+1], pf[kc], vv[2], vv[3]);
            }
        }
    }

    // ---- epilogue: normalize, fp16 out ----
    const float inv0 = 1.f / l0, inv1 = 1.f / l1;
    const size_t row0 = tokbase + w*16 + (lane >> 2);
    #pragma unroll
    for (int g = 0; g < 8; g++) {
        const int cc = coff + g*8 + (lane & 3)*2;
        *(uint32_t*)(o_g + row0*Dd + cc)     = f2h2(oacc[g][0]*inv0, oacc[g][1]*inv0);
        *(uint32_t*)(o_g + (row0+8)*Dd + cc) = f2h2(oacc[g][2]*inv1, oacc[g][3]*inv1);
    }
}

// ---------------- host orchestration ----------------------------------------
extern "C" void kernel_launch(void* const* d_in, const int* in_sizes, int n_in,
                              void* d_out, int out_size)
{
    (void)in_sizes; (void)n_in; (void)out_size;
    const float* x  = (const float*)d_in[0];
    const float* wq = (const float*)d_in[1];
    const float* bq = (const float*)d_in[2];
    const float* wk = (const float*)d_in[3];
    const float* bk = (const float*)d_in[4];
    const float* wv = (const float*)d_in[5];
    const float* bv = (const float*)d_in[6];
    const float* wo = (const float*)d_in[7];
    const float* bo = (const float*)d_in[8];
    const float* w1 = (const float*)d_in[9];
    const float* b1 = (const float*)d_in[10];
    const float* w2 = (const float*)d_in[11];
    const float* b2 = (const float*)d_in[12];
    float* out = (float*)d_out;

    float *r1, *bqkv;
    cudaGetSymbolAddress((void**)&r1,   g_r1);
    cudaGetSymbolAddress((void**)&bqkv, g_bqkv);

    __half *wqkvH,*woH,*w1H,*w2H, *hA,*yA,*fA,*oA,*qkvA;
    cudaGetSymbolAddress((void**)&wqkvH, g_wqkv);
    cudaGetSymbolAddress((void**)&woH, g_wo);
    cudaGetSymbolAddress((void**)&w1H, g_w1);
    cudaGetSymbolAddress((void**)&w2H, g_w2);
    cudaGetSymbolAddress((void**)&hA,  g_h);
    cudaGetSymbolAddress((void**)&yA,  g_y);
    cudaGetSymbolAddress((void**)&fA,  g_f);
    cudaGetSymbolAddress((void**)&oA,  g_oH);
    cudaGetSymbolAddress((void**)&qkvA, g_qkv);

    cudaFuncSetAttribute(gemm_mma<false,false,1>, cudaFuncAttributeMaxDynamicSharedMemorySize, GEMM_SMEM);
    cudaFuncSetAttribute(gemm_mma<false,true, 0>, cudaFuncAttributeMaxDynamicSharedMemorySize, GEMM_SMEM);
    cudaFuncSetAttribute(gemm_mma<true, false,1>, cudaFuncAttributeMaxDynamicSharedMemorySize, GEMM_SMEM);
    cudaFuncSetAttribute(attn_mma, cudaFuncAttributeMaxDynamicSharedMemorySize, ATT_SMEM);

    const dim3 gQKV(QKVD/128, Mrows/128);    // (24, 32)
    const dim3 gProj(Dd/128, Mrows/128);     // (8, 32)
    const dim3 gFF1(FFd/128, Mrows/128);     // (32, 32)

    // weight converts (fp32 -> fp16), 4 float4/thread
    conv_kernel<<<(Dd*Dd)/4096, 256>>>(wq, wqkvH);
    conv_kernel<<<(Dd*Dd)/4096, 256>>>(wk, wqkvH + Dd*Dd);
    conv_kernel<<<(Dd*Dd)/4096, 256>>>(wv, wqkvH + 2*Dd*Dd);
    conv_kernel<<<(Dd*Dd)/4096, 256>>>(wo, woH);
    conv_kernel<<<(FFd*Dd)/4096, 256>>>(w1, w1H);
    conv_kernel<<<(Dd*FFd)/4096, 256>>>(w2, w2H);
    bias_concat<<<QKVD/256, 256>>>(bq, bk, bv);

    // LN1 -> h (fp16)
    ln_partial<<<dim3(NPART, Bb), 256>>>(x);
    ln_final<<<Bb, 32>>>();
    ln_apply_h<<<(Mrows*Dd)/4096, 256>>>(x, hA);

    // fused QKV projection (fp16 out, [tok, 3072])
    gemm_mma<false,false,1><<<gQKV, 256, GEMM_SMEM>>>(hA, wqkvH, bqkv, nullptr, nullptr, qkvA, QKVD, Dd);

    // attention (MMA) -> fp16 o
    attn_mma<<<dim3(Ls/128, Hh, Bb), 256, ATT_SMEM>>>(qkvA, oA);

    // out-proj + residual(x) -> fp32 r1
    gemm_mma<false,true,0><<<gProj, 256, GEMM_SMEM>>>(oA, woH, bo, x, r1, nullptr, Dd, Dd);

    // LN2 -> y (fp16)
    ln_partial<<<dim3(NPART, Bb), 256>>>(r1);
    ln_final<<<Bb, 32>>>();
    ln_apply_h<<<(Mrows*Dd)/4096, 256>>>(r1, yA);

    // FFN1: relu, fp16 f
    gemm_mma<true,false,1><<<gFF1, 256, GEMM_SMEM>>>(yA, w1H, b1, nullptr, nullptr, fA, FFd, Dd);
    // FFN2: + residual(x), fp32 out
    gemm_mma<false,true,0><<<gProj, 256, GEMM_SMEM>>>(fA, w2H, b2, x, out, nullptr, Dd, FFd);
}

// round 16
// speedup vs baseline: 1.0522x; 1.0522x over previous
#include <cuda_runtime.h>
#include <cuda_fp16.h>
#include <math.h>
#include <stdint.h>

// Problem constants
#define Bb   2
#define Ls   2048
#define Dd   1024
#define Hh   16
#define DHd  64
#define FFd  4096
#define Mrows (Bb*Ls)      // 4096
#define LD    (Ls*Dd)      // 2097152
#define NPART 64

// ---------------- scratch (static device globals; no allocation) -------------
__device__ float g_r1[Mrows*Dd];
__device__ float g_part[Bb*NPART*2];

// fp16 buffers
__device__ __align__(256) __half g_wq[Dd*Dd];
__device__ __align__(256) __half g_wk[Dd*Dd];
__device__ __align__(256) __half g_wv[Dd*Dd];
__device__ __align__(256) __half g_wo[Dd*Dd];
__device__ __align__(256) __half g_w1[FFd*Dd];
__device__ __align__(256) __half g_w2[Dd*FFd];
__device__ __align__(256) __half g_h[Mrows*Dd];
__device__ __align__(256) __half g_y[Mrows*Dd];
__device__ __align__(256) __half g_f[Mrows*FFd];
__device__ __align__(256) __half g_oH[Mrows*Dd];
__device__ __align__(256) __half g_q[Mrows*Dd];
__device__ __align__(256) __half g_k[Mrows*Dd];
__device__ __align__(256) __half g_v[Mrows*Dd];

// ---------------- PTX helpers (all legal on plain sm_103) ---------------------
__device__ __forceinline__ uint32_t smem_u32(const void* p) {
    uint32_t a;
    asm("{ .reg .u64 t; cvta.to.shared.u64 t, %1; cvt.u32.u64 %0, t; }" : "=r"(a) : "l"(p));
    return a;
}
__device__ __forceinline__ void cp16(uint32_t dst, const void* src) {
    asm volatile("cp.async.cg.shared.global [%0], [%1], 16;" :: "r"(dst), "l"(src) : "memory");
}
__device__ __forceinline__ void ldsm4(uint32_t* r, uint32_t addr) {
    asm volatile("ldmatrix.sync.aligned.m8n8.x4.shared.b16 {%0,%1,%2,%3}, [%4];"
                 : "=r"(r[0]), "=r"(r[1]), "=r"(r[2]), "=r"(r[3]) : "r"(addr));
}
__device__ __forceinline__ void ldsm4t(uint32_t* r, uint32_t addr) {
    asm volatile("ldmatrix.sync.aligned.m8n8.x4.trans.shared.b16 {%0,%1,%2,%3}, [%4];"
                 : "=r"(r[0]), "=r"(r[1]), "=r"(r[2]), "=r"(r[3]) : "r"(addr));
}
__device__ __forceinline__ void mma_f16(float* c, const uint32_t* a, uint32_t b0, uint32_t b1) {
    asm volatile(
        "mma.sync.aligned.m16n8k16.row.col.f32.f16.f16.f32 "
        "{%0,%1,%2,%3}, {%4,%5,%6,%7}, {%8,%9}, {%0,%1,%2,%3};"
        : "+f"(c[0]), "+f"(c[1]), "+f"(c[2]), "+f"(c[3])
        : "r"(a[0]), "r"(a[1]), "r"(a[2]), "r"(a[3]), "r"(b0), "r"(b1));
}
__device__ __forceinline__ uint32_t f2h2(float lo, float hi) {
    __half2 t = __floats2half2_rn(lo, hi);
    return *reinterpret_cast<uint32_t*>(&t);
}
__device__ __forceinline__ float ex2(float x) {
    float r;
    asm("ex2.approx.f32 %0, %1;" : "=f"(r) : "f"(x));
    return r;
}
#define SCL_LOG2 0.36067376022224085f   // 0.25 * log2(e)

// ---------------- merged fp32 -> fp16 weight convert (one launch) -------------
// Segments (float4 units): wq|wk|wv|wo @ 262144 each, then w1 @ 1048576, w2 @ 1048576.
#define SEG1 262144
#define CONV_TOT (4*SEG1 + 2*1048576)   // 3145728 float4
__global__ void conv_all(const float* __restrict__ wq, const float* __restrict__ wk,
                         const float* __restrict__ wv, const float* __restrict__ wo,
                         const float* __restrict__ w1, const float* __restrict__ w2) {
    const int idx = blockIdx.x * 256 + threadIdx.x;   // float4 index
    const float* src;
    __half* dst;
    int off;
    if (idx < 4*SEG1) {
        const int seg = idx >> 18;            // /SEG1
        off = idx & (SEG1 - 1);
        src = (seg == 0) ? wq : (seg == 1) ? wk : (seg == 2) ? wv : wo;
        dst = (seg == 0) ? g_wq : (seg == 1) ? g_wk : (seg == 2) ? g_wv : g_wo;
    } else if (idx < 4*SEG1 + 1048576) {
        off = idx - 4*SEG1; src = w1; dst = g_w1;
    } else {
        off = idx - 4*SEG1 - 1048576; src = w2; dst = g_w2;
    }
    float4 v = ((const float4*)src)[off];
    ((uint32_t*)dst)[2*off]   = f2h2(v.x, v.y);
    ((uint32_t*)dst)[2*off+1] = f2h2(v.z, v.w);
}

// ---------------- LayerNorm over (L,D) jointly per batch ---------------------
__global__ void ln_partial(const float* __restrict__ x) {
    const int b = blockIdx.y;
    const int tid = threadIdx.x;
    const int chunk4 = (LD / NPART) / 4;
    const float4* xp = (const float4*)(x + (size_t)b * LD) + (size_t)blockIdx.x * chunk4;
    float s = 0.f, s2 = 0.f;
    for (int i = tid; i < chunk4; i += 256) {
        float4 v = xp[i];
        s  += v.x + v.y + v.z + v.w;
        s2 += v.x*v.x + v.y*v.y + v.z*v.z + v.w*v.w;
    }
    __shared__ float sh[2][256];
    sh[0][tid] = s; sh[1][tid] = s2;
    __syncthreads();
    for (int st = 128; st > 0; st >>= 1) {
        if (tid < st) { sh[0][tid] += sh[0][tid+st]; sh[1][tid] += sh[1][tid+st]; }
        __syncthreads();
    }
    if (tid == 0) {
        g_part[(b*NPART + blockIdx.x)*2 + 0] = sh[0][0];
        g_part[(b*NPART + blockIdx.x)*2 + 1] = sh[1][0];
    }
}

// normalize, emit fp16; finalizes stats locally from g_part (no ln_final launch)
__global__ void ln_apply_h(const float* __restrict__ in, __half* __restrict__ outp) {
    const int idx = blockIdx.x * 256 + threadIdx.x;   // float4 index
    const int b = blockIdx.x >> 11;                   // 2048 blocks per batch
    __shared__ float sh[2][64];
    __shared__ float st[2];
    if (threadIdx.x < 64) {
        sh[0][threadIdx.x] = g_part[(b*NPART + threadIdx.x)*2 + 0];
        sh[1][threadIdx.x] = g_part[(b*NPART + threadIdx.x)*2 + 1];
    }
    __syncthreads();
    if (threadIdx.x < 32) {
        float s  = sh[0][threadIdx.x] + sh[0][threadIdx.x + 32];
        float s2 = sh[1][threadIdx.x] + sh[1][threadIdx.x + 32];
        #pragma unroll
        for (int o = 16; o; o >>= 1) {
            s  += __shfl_xor_sync(0xffffffffu, s,  o);
            s2 += __shfl_xor_sync(0xffffffffu, s2, o);
        }
        if (threadIdx.x == 0) {
            const float mu  = s / (float)LD;
            const float var = s2 / (float)LD - mu*mu;
            st[0] = mu;
            st[1] = rsqrtf(var + 1e-5f);
        }
    }
    __syncthreads();
    const float mu = st[0], rs = st[1];
    float4 v = ((const float4*)in)[idx];
    ((uint32_t*)outp)[2*idx]   = f2h2((v.x - mu)*rs, (v.y - mu)*rs);
    ((uint32_t*)outp)[2*idx+1] = f2h2((v.z - mu)*rs, (v.w - mu)*rs);
}

// ---------------- mma.sync fp16 GEMM ------------------------------------------
// C[M,N] = A[M,K] @ W[N,K]^T, fp32 accum, 128x128 tile, BK=32, 3-stage cp.async.
#define TILE_B   10240              // 128 * 80
#define STAGE_B  (2*TILE_B)         // 20480
#define GEMM_SMEM (3*STAGE_B)       // 61440

// OUT: 0 = fp32 C, 1 = fp16 Ch
template<bool RELU, bool RESID, int OUT>
__global__ __launch_bounds__(256)
void gemm_mma(const __half* __restrict__ A, const __half* __restrict__ W,
              const float* __restrict__ bias, const float* __restrict__ R,
              float* __restrict__ C, __half* __restrict__ Ch,
              int Ndim, int Kdim)
{
    extern __shared__ char smem[];
    const uint32_t sb = smem_u32(smem);
    const int tid  = threadIdx.x;
    const int wid  = tid >> 5, lane = tid & 31;
    const int wm   = wid & 3;
    const int wn   = wid >> 2;
    const int bm   = blockIdx.y * 128, bn = blockIdx.x * 128;

    float acc[2][8][4];
    #pragma unroll
    for (int i = 0; i < 2; i++)
        #pragma unroll
        for (int j = 0; j < 8; j++)
            #pragma unroll
            for (int t = 0; t < 4; t++) acc[i][j][t] = 0.f;

    const int r0c = tid >> 2, c0c = tid & 3;
    const int r1c = (tid + 256) >> 2, c1c = tid & 3;

    auto load_stage = [&](int s, int k0) {
        const uint32_t st = sb + s * STAGE_B;
        cp16(st + 0*TILE_B + r0c*80 + c0c*16, A + (size_t)(bm + r0c)*Kdim + k0 + c0c*8);
        cp16(st + 0*TILE_B + r1c*80 + c1c*16, A + (size_t)(bm + r1c)*Kdim + k0 + c1c*8);
        cp16(st + 1*TILE_B + r0c*80 + c0c*16, W + (size_t)(bn + r0c)*Kdim + k0 + c0c*8);
        cp16(st + 1*TILE_B + r1c*80 + c1c*16, W + (size_t)(bn + r1c)*Kdim + k0 + c1c*8);
        asm volatile("cp.async.commit_group;" ::: "memory");
    };

    const int nk = Kdim >> 5;
    load_stage(0, 0);
    load_stage(1, 32);

    for (int kt = 0; kt < nk; kt++) {
        if (kt + 1 < nk) { asm volatile("cp.async.wait_group 1;" ::: "memory"); }
        else             { asm volatile("cp.async.wait_group 0;" ::: "memory"); }
        __syncthreads();
        if (kt + 2 < nk) load_stage((kt + 2) % 3, (kt + 2) << 5);

        const uint32_t st = sb + (kt % 3) * STAGE_B;
        #pragma unroll
        for (int ks = 0; ks < 2; ks++) {
            const uint32_t koff = ks*32 + ((lane >> 4) & 1)*16;
            uint32_t a[2][4];
            #pragma unroll
            for (int mt = 0; mt < 2; mt++)
                ldsm4(a[mt], st + (wm*32 + mt*16 + (lane & 15))*80 + koff);
            #pragma unroll
            for (int g = 0; g < 4; g++) {
                const uint32_t rb = st + TILE_B + (wn*64 + g*16 + (lane & 15))*80 + koff;
                uint32_t wv[4];
                ldsm4(wv, rb);
                #pragma unroll
                for (int mt = 0; mt < 2; mt++) {
                    mma_f16(acc[mt][2*g],   a[mt], wv[0], wv[2]);
                    mma_f16(acc[mt][2*g+1], a[mt], wv[1], wv[3]);
                }
            }
        }
    }

    // ---- epilogue ----
    #pragma unroll
    for (int mt = 0; mt < 2; mt++) {
        const int row0 = bm + wm*32 + mt*16 + (lane >> 2);
        #pragma unroll
        for (int nt = 0; nt < 8; nt++) {
            const int cc = bn + wn*64 + nt*8 + (lane & 3)*2;
            const float b0 = bias[cc], b1 = bias[cc+1];
            float v00 = acc[mt][nt][0] + b0, v01 = acc[mt][nt][1] + b1;
            float v10 = acc[mt][nt][2] + b0, v11 = acc[mt][nt][3] + b1;
            if (RESID) {
                v00 += R[(size_t)row0*Ndim + cc];     v01 += R[(size_t)row0*Ndim + cc + 1];
                v10 += R[(size_t)(row0+8)*Ndim + cc]; v11 += R[(size_t)(row0+8)*Ndim + cc + 1];
            }
            if (RELU) {
                v00 = fmaxf(v00, 0.f); v01 = fmaxf(v01, 0.f);
                v10 = fmaxf(v10, 0.f); v11 = fmaxf(v11, 0.f);
            }
            if (OUT == 0) {
                *(float2*)(C + (size_t)row0*Ndim + cc)     = {v00, v01};
                *(float2*)(C + (size_t)(row0+8)*Ndim + cc) = {v10, v11};
            } else {
                *(uint32_t*)(Ch + (size_t)row0*Ndim + cc)     = f2h2(v00, v01);
                *(uint32_t*)(Ch + (size_t)(row0+8)*Ndim + cc) = f2h2(v10, v11);
            }
        }
    }
}

// ---------------- MMA flash attention (single-term fp16, exp2 softmax) --------
#define AST 144
#define ATT_Q  0
#define ATT_S0 (128*AST)             // 18432
#define ATT_STAGE (2*64*AST)         // 18432 (K tile + V tile)
#define ATT_Vo (64*AST)
#define ATT_SMEM (ATT_S0 + 3*ATT_STAGE)   // 73728

__global__ __launch_bounds__(256)
void attn_mma(const __half* __restrict__ q_g, const __half* __restrict__ k_g,
              const __half* __restrict__ v_g, __half* __restrict__ o_g)
{
    extern __shared__ char smem[];
    const uint32_t sb = smem_u32(smem);
    const int tid = threadIdx.x, w = tid >> 5, lane = tid & 31;
    const int b = blockIdx.z, h = blockIdx.y, q0 = blockIdx.x * 128;
    const size_t tokbase = (size_t)(b*Ls + q0);
    const int coff = h * DHd;

    // load Q tile, 128 rows x 128B
    #pragma unroll
    for (int it = 0; it < 4; it++) {
        const int unit = tid + it*256;
        const int r = unit >> 3, c = unit & 7;
        cp16(sb + ATT_Q + r*AST + c*16, q_g + (tokbase + r)*Dd + coff + c*8);
    }
    asm volatile("cp.async.commit_group;" ::: "memory");

    auto load_kv = [&](int s, int t0) {
        const uint32_t st = sb + ATT_S0 + s*ATT_STAGE;
        const size_t kb = (size_t)(b*Ls + t0);
        #pragma unroll
        for (int it = 0; it < 2; it++) {
            const int unit = tid + it*256;
            const int r = unit >> 3, c = unit & 7;
            cp16(st + r*AST + c*16,          k_g + (kb + r)*Dd + coff + c*8);
            cp16(st + ATT_Vo + r*AST + c*16, v_g + (kb + r)*Dd + coff + c*8);
        }
        asm volatile("cp.async.commit_group;" ::: "memory");
    };

    load_kv(0, 0);
    load_kv(1, 64);
    asm volatile("cp.async.wait_group 1;" ::: "memory");   // Q + kv0 ready
    __syncthreads();

    // Q fragments in registers (A operand, m16 rows = w*16)
    uint32_t qf[4][4];
    #pragma unroll
    for (int kc = 0; kc < 4; kc++)
        ldsm4(qf[kc], sb + ATT_Q + (w*16 + (lane & 15))*AST + kc*32 + ((lane >> 4) & 1)*16);

    float oacc[8][4];
    #pragma unroll
    for (int g = 0; g < 8; g++)
        #pragma unroll
        for (int i = 0; i < 4; i++) oacc[g][i] = 0.f;
    float m0 = -1e30f, m1 = -1e30f, l0 = 0.f, l1 = 0.f;

    const int nt = Ls/64;
    for (int t = 0; t < nt; t++) {
        if (t > 0) {
            if (t + 1 < nt) { asm volatile("cp.async.wait_group 1;" ::: "memory"); }
            else            { asm volatile("cp.async.wait_group 0;" ::: "memory"); }
            __syncthreads();
        }
        if (t + 2 < nt) load_kv((t + 2) % 3, (t + 2) * 64);
        const uint32_t st = sb + ATT_S0 + (t % 3)*ATT_STAGE;

        // ---- S = Q @ K^T ----
        float sc[8][4];
        #pragma unroll
        for (int g = 0; g < 8; g++)
            #pragma unroll
            for (int i = 0; i < 4; i++) sc[g][i] = 0.f;
        #pragma unroll
        for (int ng = 0; ng < 4; ng++) {
            #pragma unroll
            for (int kc = 0; kc < 4; kc++) {
                uint32_t bh[4];
                ldsm4(bh, st + (ng*16 + (lane & 15))*AST + kc*32 + ((lane >> 4) & 1)*16);
                mma_f16(sc[2*ng],   qf[kc], bh[0], bh[2]);
                mma_f16(sc[2*ng+1], qf[kc], bh[1], bh[3]);
            }
        }

        // ---- online softmax in log2 domain (scale folded: 0.25*log2e) ----
        float rm0 = -1e30f, rm1 = -1e30f;
        #pragma unroll
        for (int g = 0; g < 8; g++) {
            sc[g][0] *= SCL_LOG2; sc[g][1] *= SCL_LOG2;
            sc[g][2] *= SCL_LOG2; sc[g][3] *= SCL_LOG2;
            rm0 = fmaxf(rm0, fmaxf(sc[g][0], sc[g][1]));
            rm1 = fmaxf(rm1, fmaxf(sc[g][2], sc[g][3]));
        }
        rm0 = fmaxf(rm0, __shfl_xor_sync(0xffffffffu, rm0, 1));
        rm0 = fmaxf(rm0, __shfl_xor_sync(0xffffffffu, rm0, 2));
        rm1 = fmaxf(rm1, __shfl_xor_sync(0xffffffffu, rm1, 1));
        rm1 = fmaxf(rm1, __shfl_xor_sync(0xffffffffu, rm1, 2));
        const float nm0 = fmaxf(m0, rm0), nm1 = fmaxf(m1, rm1);
        const float c0 = ex2(m0 - nm0), c1 = ex2(m1 - nm1);
        m0 = nm0; m1 = nm1;

        float ls0 = 0.f, ls1 = 0.f;
        uint32_t pf[4][4];
        #pragma unroll
        for (int g = 0; g < 8; g++) {
            const float p0 = ex2(sc[g][0] - m0);
            const float p1 = ex2(sc[g][1] - m0);
            const float p2 = ex2(sc[g][2] - m1);
            const float p3 = ex2(sc[g][3] - m1);
            ls0 += p0 + p1; ls1 += p2 + p3;
            const uint32_t hp01 = f2h2(p0, p1), hp23 = f2h2(p2, p3);
            const int kc = g >> 1;
            if ((g & 1) == 0) { pf[kc][0] = hp01; pf[kc][1] = hp23; }
            else              { pf[kc][2] = hp01; pf[kc][3] = hp23; }
            oacc[g][0] *= c0; oacc[g][1] *= c0; oacc[g][2] *= c1; oacc[g][3] *= c1;
        }
        ls0 += __shfl_xor_sync(0xffffffffu, ls0, 1);
        ls0 += __shfl_xor_sync(0xffffffffu, ls0, 2);
        ls1 += __shfl_xor_sync(0xffffffffu, ls1, 1);
        ls1 += __shfl_xor_sync(0xffffffffu, ls1, 2);
        l0 = l0*c0 + ls0; l1 = l1*c1 + ls1;

        // ---- O += P @ V, V^T via ldmatrix.trans ----
        #pragma unroll
        for (int ng = 0; ng < 4; ng++) {
            #pragma unroll
            for (int kc = 0; kc < 4; kc++) {
                uint32_t vv[4];
                ldsm4t(vv, st + ATT_Vo + (kc*16 + (lane & 15))*AST + ng*32 + ((lane >> 4) & 1)*16);
                mma_f16(oacc[2*ng],   pf[kc], vv[0], vv[1]);
                mma_f16(oacc[2*ng+1], pf[kc], vv[2], vv[3]);
            }
        }
    }

    // ---- epilogue: normalize, fp16 out ----
    const float inv0 = 1.f / l0, inv1 = 1.f / l1;
    const size_t row0 = tokbase + w*16 + (lane >> 2);
    #pragma unroll
    for (int g = 0; g < 8; g++) {
        const int cc = coff + g*8 + (lane & 3)*2;
        *(uint32_t*)(o_g + row0*Dd + cc)     = f2h2(oacc[g][0]*inv0, oacc[g][1]*inv0);
        *(uint32_t*)(o_g + (row0+8)*Dd + cc) = f2h2(oacc[g][2]*inv1, oacc[g][3]*inv1);
    }
}

// ---------------- host orchestration ----------------------------------------
extern "C" void kernel_launch(void* const* d_in, const int* in_sizes, int n_in,
                              void* d_out, int out_size)
{
    (void)in_sizes; (void)n_in; (void)out_size;
    const float* x  = (const float*)d_in[0];
    const float* wq = (const float*)d_in[1];
    const float* bq = (const float*)d_in[2];
    const float* wk = (const float*)d_in[3];
    const float* bk = (const float*)d_in[4];
    const float* wv = (const float*)d_in[5];
    const float* bv = (const float*)d_in[6];
    const float* wo = (const float*)d_in[7];
    const float* bo = (const float*)d_in[8];
    const float* w1 = (const float*)d_in[9];
    const float* b1 = (const float*)d_in[10];
    const float* w2 = (const float*)d_in[11];
    const float* b2 = (const float*)d_in[12];
    float* out = (float*)d_out;

    float *r1;
    cudaGetSymbolAddress((void**)&r1, g_r1);

    __half *wqH,*wkH,*wvH,*woH,*w1H,*w2H, *hA,*yA,*fA,*oA,*qA,*kA,*vA;
    cudaGetSymbolAddress((void**)&wqH, g_wq);
    cudaGetSymbolAddress((void**)&wkH, g_wk);
    cudaGetSymbolAddress((void**)&wvH, g_wv);
    cudaGetSymbolAddress((void**)&woH, g_wo);
    cudaGetSymbolAddress((void**)&w1H, g_w1);
    cudaGetSymbolAddress((void**)&w2H, g_w2);
    cudaGetSymbolAddress((void**)&hA,  g_h);
    cudaGetSymbolAddress((void**)&yA,  g_y);
    cudaGetSymbolAddress((void**)&fA,  g_f);
    cudaGetSymbolAddress((void**)&oA,  g_oH);
    cudaGetSymbolAddress((void**)&qA,  g_q);
    cudaGetSymbolAddress((void**)&kA,  g_k);
    cudaGetSymbolAddress((void**)&vA,  g_v);

    cudaFuncSetAttribute(gemm_mma<false,false,1>, cudaFuncAttributeMaxDynamicSharedMemorySize, GEMM_SMEM);
    cudaFuncSetAttribute(gemm_mma<false,true, 0>, cudaFuncAttributeMaxDynamicSharedMemorySize, GEMM_SMEM);
    cudaFuncSetAttribute(gemm_mma<true, false,1>, cudaFuncAttributeMaxDynamicSharedMemorySize, GEMM_SMEM);
    cudaFuncSetAttribute(attn_mma, cudaFuncAttributeMaxDynamicSharedMemorySize, ATT_SMEM);

    const dim3 gProj(Dd/128, Mrows/128);     // (8, 32)
    const dim3 gFF1(FFd/128, Mrows/128);     // (32, 32)

    // merged weight convert (single launch, full grid width)
    conv_all<<<CONV_TOT/256, 256>>>(wq, wk, wv, wo, w1, w2);

    // LN1 -> h (fp16); stats finalized inside ln_apply_h
    ln_partial<<<dim3(NPART, Bb), 256>>>(x);
    ln_apply_h<<<(Mrows*Dd)/4/256, 256>>>(x, hA);

    // QKV projections (fp16 out)
    gemm_mma<false,false,1><<<gProj, 256, GEMM_SMEM>>>(hA, wqH, bq, nullptr, nullptr, qA, Dd, Dd);
    gemm_mma<false,false,1><<<gProj, 256, GEMM_SMEM>>>(hA, wkH, bk, nullptr, nullptr, kA, Dd, Dd);
    gemm_mma<false,false,1><<<gProj, 256, GEMM_SMEM>>>(hA, wvH, bv, nullptr, nullptr, vA, Dd, Dd);

    // attention (MMA) -> fp16 o
    attn_mma<<<dim3(Ls/128, Hh, Bb), 256, ATT_SMEM>>>(qA, kA, vA, oA);

    // out-proj + residual(x) -> fp32 r1
    gemm_mma<false,true,0><<<gProj, 256, GEMM_SMEM>>>(oA, woH, bo, x, r1, nullptr, Dd, Dd);

    // LN2 -> y (fp16)
    ln_partial<<<dim3(NPART, Bb), 256>>>(r1);
    ln_apply_h<<<(Mrows*Dd)/4/256, 256>>>(r1, yA);

    // FFN1: relu, fp16 f
    gemm_mma<true,false,1><<<gFF1, 256, GEMM_SMEM>>>(yA, w1H, b1, nullptr, nullptr, fA, FFd, Dd);
    // FFN2: + residual(x), fp32 out
    gemm_mma<false,true,0><<<gProj, 256, GEMM_SMEM>>>(fA, w2H, b2, x, out, nullptr, Dd, FFd);
}